// round 1
// baseline (speedup 1.0000x reference)
#include <cuda_runtime.h>

// HolographicLayer: eta = dot(R[p], ccorr_half(E[s], E[o]))
//   ccorr_half(a,b)[k] = sum_i a[k+i-100] * b[i],  zero-padded, d=201
// Only x[0,:] = (s, o, p) is used. Output: 1 float scalar.

#define D 201
#define PAD 100
#define NTHREADS 256

__global__ void holo_kernel(const int* __restrict__ x,
                            const float* __restrict__ E,
                            const float* __restrict__ R,
                            float* __restrict__ out) {
    __shared__ float s2v[D];
    __shared__ float o2v[D];
    __shared__ float r2v[D];
    __shared__ float partial[NTHREADS];

    const int t = threadIdx.x;

    // x is [32,3] row-major; row 0 = (s, o, p)
    const int s = x[0];
    const int o = x[1];
    const int p = x[2];

    const float* __restrict__ Es = E + (long long)s * D;
    const float* __restrict__ Eo = E + (long long)o * D;
    const float* __restrict__ Rp = R + (long long)p * D;

    if (t < D) {
        s2v[t] = Es[t];
        o2v[t] = Eo[t];
        r2v[t] = Rp[t];
    }
    __syncthreads();

    float acc = 0.0f;
    if (t < D) {
        const int k = t;
        // valid j = k + i - PAD must be in [0, D)
        const int i0 = (k >= PAD) ? 0 : (PAD - k);
        const int i1 = (D + PAD - k < D) ? (D + PAD - k) : D;
        float inner = 0.0f;
        #pragma unroll 4
        for (int i = i0; i < i1; i++) {
            inner = fmaf(s2v[k + i - PAD], o2v[i], inner);
        }
        acc = r2v[k] * inner;
    }

    partial[t] = acc;
    __syncthreads();

    #pragma unroll
    for (int sft = NTHREADS / 2; sft >= 32; sft >>= 1) {
        if (t < sft) partial[t] += partial[t + sft];
        __syncthreads();
    }
    if (t < 32) {
        float v = partial[t];
        #pragma unroll
        for (int off = 16; off > 0; off >>= 1)
            v += __shfl_down_sync(0xFFFFFFFFu, v, off);
        if (t == 0) out[0] = v;
    }
}

extern "C" void kernel_launch(void* const* d_in, const int* in_sizes, int n_in,
                              void* d_out, int out_size) {
    const int*   x = (const int*)d_in[0];
    const float* E = (const float*)d_in[1];
    const float* R = (const float*)d_in[2];
    float* out = (float*)d_out;
    holo_kernel<<<1, NTHREADS>>>(x, E, R, out);
}

// round 3
// speedup vs baseline: 1.0500x; 1.0500x over previous
#include <cuda_runtime.h>

// HolographicLayer: eta = dot(R[p], ccorr_half(E[s], E[o]))
//   ccorr_half(a,b)[k] = sum_i a[k+i-100] * b[i], zero-padded, d=201
// Reformulated with zero-padded smem operand sp (sp[100+j] = a[j]):
//   eta = sum_k rv[k] * sum_i sp[k+i] * bv[i]
// Work split: 8 blocks each own a 26-wide chunk of i; thread t owns k=t.
// Cross-block reduction via device-global partials + atomic ticket.

#define D      201
#define PAD    100
#define NB     8
#define NT     256
#define CHUNK  26      // NB*CHUNK = 208 >= 201, bv zero-padded beyond
#define SPLEN  512     // max index: k(255) + i(207) = 462 < 512

__device__ float        g_partials[NB];
__device__ unsigned int g_count = 0;

__global__ void holo_kernel(const int* __restrict__ x,
                            const float* __restrict__ E,
                            const float* __restrict__ R,
                            float* __restrict__ out) {
    __shared__ float sp[SPLEN];
    __shared__ float bv[NT];
    __shared__ float rv[NT];
    __shared__ float wsum[NT / 32];

    const int t   = threadIdx.x;
    const int blk = blockIdx.x;

    // x is [32,3] row-major; row 0 = (s, o, p)
    const int s = x[0], o = x[1], p = x[2];
    const float* __restrict__ Es = E + (long long)s * D;
    const float* __restrict__ Eo = E + (long long)o * D;
    const float* __restrict__ Rp = R + (long long)p * D;

    // Single-pass padded loads (one sync total). All gathers issued
    // up-front so DRAM latency is paid once, overlapped across blocks.
    bv[t] = (t < D) ? Eo[t] : 0.0f;
    rv[t] = (t < D) ? Rp[t] : 0.0f;
    #pragma unroll
    for (int m = t; m < SPLEN; m += NT) {
        const int j = m - PAD;
        sp[m] = (j >= 0 && j < D) ? Es[j] : 0.0f;
    }
    __syncthreads();

    // Thread t computes partial ccorr contribution for k = t over this
    // block's i-chunk. Fully unrolled, two accumulators to break the
    // FMA dependency chain. sp access: consecutive lanes -> consecutive
    // banks (conflict-free); bv access: uniform -> broadcast.
    const int i0 = blk * CHUNK;
    float a0 = 0.0f, a1 = 0.0f;
    #pragma unroll
    for (int i = 0; i < CHUNK; i += 2) {
        a0 = fmaf(sp[t + i0 + i],     bv[i0 + i],     a0);
        a1 = fmaf(sp[t + i0 + i + 1], bv[i0 + i + 1], a1);
    }
    float v = rv[t] * (a0 + a1);   // rv zero-padded: k >= 201 contributes 0

    // Block reduce 256 -> 1
    #pragma unroll
    for (int off = 16; off > 0; off >>= 1)
        v += __shfl_down_sync(0xFFFFFFFFu, v, off);
    if ((t & 31) == 0) wsum[t >> 5] = v;
    __syncthreads();

    if (t < 32) {
        float w = (t < NT / 32) ? wsum[t] : 0.0f;
        #pragma unroll
        for (int off = 4; off > 0; off >>= 1)
            w += __shfl_down_sync(0xFFFFFFFFu, w, off);

        if (t == 0) {
            g_partials[blk] = w;
            __threadfence();
            const unsigned int ticket = atomicAdd(&g_count, 1u);
            if (ticket == NB - 1) {           // last block finalizes
                __threadfence();
                float total = 0.0f;
                #pragma unroll
                for (int b = 0; b < NB; b++) total += g_partials[b];
                out[0] = total;
                g_count = 0;                  // reset for next graph replay
            }
        }
    }
}

extern "C" void kernel_launch(void* const* d_in, const int* in_sizes, int n_in,
                              void* d_out, int out_size) {
    const int*   x = (const int*)d_in[0];
    const float* E = (const float*)d_in[1];
    const float* R = (const float*)d_in[2];
    float* out = (float*)d_out;
    holo_kernel<<<NB, NT>>>(x, E, R, out);
}

// round 4
// speedup vs baseline: 1.0694x; 1.0185x over previous
#include <cuda_runtime.h>

// HolographicLayer: eta = dot(R[p], ccorr_half(E[s], E[o]))
//   ccorr_half(a,b)[k] = sum_i a[k+i-100] * b[i], zero-padded, d=201
// With padded smem sp (sp[100+j] = a[j], zeros elsewhere):
//   eta = sum_k rv[k] * sum_i sp[k+i] * bv[i]
// Single block. Thread t owns a 4-k x 44-i register tile:
//   tc = t/51 (i-chunk), tk = t%51 (k-group of 4).
// Per 4 i's: 2x LDS.128 (sp sliding window) + 1x LDS.128 (bv) -> 16 FMAs.
// All arrays zero-padded to 512 so no bounds checks anywhere.

#define D    201
#define PAD  100
#define NT   256

__global__ void holo_kernel(const int* __restrict__ x,
                            const float* __restrict__ E,
                            const float* __restrict__ R,
                            float* __restrict__ out) {
    __shared__ __align__(16) float sp[512];
    __shared__ __align__(16) float bv[512];
    __shared__ __align__(16) float rv[512];
    __shared__ float wsum[NT / 32];

    const int t = threadIdx.x;

    // x is [32,3] row-major; row 0 = (s, o, p)
    const int s = x[0], o = x[1], p = x[2];
    const float* __restrict__ Es = E + (long long)s * D;
    const float* __restrict__ Eo = E + (long long)o * D;
    const float* __restrict__ Rp = R + (long long)p * D;

    // Zero-padded fills, one pass, one sync.
    #pragma unroll
    for (int m = t; m < 512; m += NT) {
        sp[m] = (m >= PAD && m < PAD + D) ? Es[m - PAD] : 0.0f;
        bv[m] = (m < D) ? Eo[m] : 0.0f;
        rv[m] = (m < D) ? Rp[m] : 0.0f;
    }
    __syncthreads();

    // Tile coordinates: 51 k-groups x 5 i-chunks = 255 threads; the one
    // extra thread lands in chunk 5 (i in [220,264)) where bv == 0.
    const int tc = t / 51;            // i-chunk: 0..5
    const int tk = t - tc * 51;       // k-group: 0..50
    const int k0 = tk * 4;            // k0 multiple of 4 (16B aligned)
    const int ci = tc * 44;           // chunk start, multiple of 4

    float a0 = 0.0f, a1 = 0.0f, a2 = 0.0f, a3 = 0.0f;
    #pragma unroll
    for (int j = 0; j < 44; j += 4) {
        const int idx = k0 + ci + j;                       // 16B aligned
        const float4 s0 = *reinterpret_cast<const float4*>(&sp[idx]);
        const float4 s1 = *reinterpret_cast<const float4*>(&sp[idx + 4]);
        const float4 b4 = *reinterpret_cast<const float4*>(&bv[ci + j]);

        a0 = fmaf(s0.x, b4.x, a0); a0 = fmaf(s0.y, b4.y, a0);
        a0 = fmaf(s0.z, b4.z, a0); a0 = fmaf(s0.w, b4.w, a0);

        a1 = fmaf(s0.y, b4.x, a1); a1 = fmaf(s0.z, b4.y, a1);
        a1 = fmaf(s0.w, b4.z, a1); a1 = fmaf(s1.x, b4.w, a1);

        a2 = fmaf(s0.z, b4.x, a2); a2 = fmaf(s0.w, b4.y, a2);
        a2 = fmaf(s1.x, b4.z, a2); a2 = fmaf(s1.y, b4.w, a2);

        a3 = fmaf(s0.w, b4.x, a3); a3 = fmaf(s1.x, b4.y, a3);
        a3 = fmaf(s1.y, b4.z, a3); a3 = fmaf(s1.z, b4.w, a3);
    }

    // Fold in rv (zero-padded beyond k=200, so spare groups vanish).
    const float4 r4 = *reinterpret_cast<const float4*>(&rv[k0]);
    float v = r4.x * a0;
    v = fmaf(r4.y, a1, v);
    v = fmaf(r4.z, a2, v);
    v = fmaf(r4.w, a3, v);

    // Block reduce 256 -> 1 (shfl within warps, then warp 0).
    #pragma unroll
    for (int off = 16; off > 0; off >>= 1)
        v += __shfl_down_sync(0xFFFFFFFFu, v, off);
    if ((t & 31) == 0) wsum[t >> 5] = v;
    __syncthreads();

    if (t < 32) {
        float w = (t < NT / 32) ? wsum[t] : 0.0f;
        #pragma unroll
        for (int off = 4; off > 0; off >>= 1)
            w += __shfl_down_sync(0xFFFFFFFFu, w, off);
        if (t == 0) out[0] = w;
    }
}

extern "C" void kernel_launch(void* const* d_in, const int* in_sizes, int n_in,
                              void* d_out, int out_size) {
    const int*   x = (const int*)d_in[0];
    const float* E = (const float*)d_in[1];
    const float* R = (const float*)d_in[2];
    float* out = (float*)d_out;
    holo_kernel<<<1, NT>>>(x, E, R, out);
}

// round 5
// speedup vs baseline: 1.1106x; 1.0385x over previous
#include <cuda_runtime.h>

// HolographicLayer: eta = dot(R[p], ccorr_half(E[s], E[o]))
//   ccorr_half(a,b)[k] = sum_i a[k+i-100] * b[i], zero-padded, d=201
// With padded smem sp (sp[100+j] = a[j], zeros elsewhere):
//   eta = sum_k rv[k] * sum_i sp[k+i] * bv[i]
// Single block. Thread t owns a 4-k x 44-i register tile:
//   tc = t/51 (i-chunk), tk = t%51 (k-group of 4).
// Per 4 i's: 2x LDS.128 (sp sliding window) + 1x LDS.128 (bv) -> 16 FMAs.
// rv is NOT staged in smem: each thread loads its own 4 R values from
// global right after p is known, overlapping the fill + compute phases.

#define D    201
#define PAD  100
#define NT   256

__global__ void holo_kernel(const int* __restrict__ x,
                            const float* __restrict__ E,
                            const float* __restrict__ R,
                            float* __restrict__ out) {
    __shared__ __align__(16) float sp[512];
    __shared__ __align__(16) float bv[512];
    __shared__ float wsum[NT / 32];

    const int t = threadIdx.x;

    // x is [32,3] row-major; row 0 = (s, o, p)
    const int s = x[0], o = x[1], p = x[2];
    const float* __restrict__ Es = E + (long long)s * D;
    const float* __restrict__ Eo = E + (long long)o * D;
    const float* __restrict__ Rp = R + (long long)p * D;

    // Tile coordinates: 51 k-groups x 5 i-chunks = 255 threads; the one
    // extra thread lands in chunk 5 (i in [220,264)) where bv == 0.
    const int tc = t / 51;            // i-chunk: 0..5
    const int tk = t - tc * 51;       // k-group: 0..50
    const int k0 = tk * 4;            // k0 multiple of 4 (16B aligned)
    const int ci = tc * 44;           // chunk start, multiple of 4

    // Issue the per-thread R gathers NOW; consumed only after the compute
    // loop, so their latency hides under the fill + barrier + FMAs.
    // Guarded: k0+c can reach 203 > 200 (OOB for the last R row).
    const float r0 = Rp[k0];
    const float r1 = (k0 + 1 < D) ? Rp[k0 + 1] : 0.0f;
    const float r2 = (k0 + 2 < D) ? Rp[k0 + 2] : 0.0f;
    const float r3 = (k0 + 3 < D) ? Rp[k0 + 3] : 0.0f;

    // Zero-padded fills, one pass, one sync.
    #pragma unroll
    for (int m = t; m < 512; m += NT) {
        sp[m] = (m >= PAD && m < PAD + D) ? Es[m - PAD] : 0.0f;
        bv[m] = (m < D) ? Eo[m] : 0.0f;
    }
    __syncthreads();

    float a0 = 0.0f, a1 = 0.0f, a2 = 0.0f, a3 = 0.0f;
    #pragma unroll
    for (int j = 0; j < 44; j += 4) {
        const int idx = k0 + ci + j;                       // 16B aligned
        const float4 s0 = *reinterpret_cast<const float4*>(&sp[idx]);
        const float4 s1 = *reinterpret_cast<const float4*>(&sp[idx + 4]);
        const float4 b4 = *reinterpret_cast<const float4*>(&bv[ci + j]);

        a0 = fmaf(s0.x, b4.x, a0); a0 = fmaf(s0.y, b4.y, a0);
        a0 = fmaf(s0.z, b4.z, a0); a0 = fmaf(s0.w, b4.w, a0);

        a1 = fmaf(s0.y, b4.x, a1); a1 = fmaf(s0.z, b4.y, a1);
        a1 = fmaf(s0.w, b4.z, a1); a1 = fmaf(s1.x, b4.w, a1);

        a2 = fmaf(s0.z, b4.x, a2); a2 = fmaf(s0.w, b4.y, a2);
        a2 = fmaf(s1.x, b4.z, a2); a2 = fmaf(s1.y, b4.w, a2);

        a3 = fmaf(s0.w, b4.x, a3); a3 = fmaf(s1.x, b4.y, a3);
        a3 = fmaf(s1.y, b4.z, a3); a3 = fmaf(s1.z, b4.w, a3);
    }

    // Fold in rv (spare chunk's accumulators are all zero).
    float v = r0 * a0;
    v = fmaf(r1, a1, v);
    v = fmaf(r2, a2, v);
    v = fmaf(r3, a3, v);

    // Block reduce 256 -> 1 (shfl within warps, then warp 0).
    #pragma unroll
    for (int off = 16; off > 0; off >>= 1)
        v += __shfl_down_sync(0xFFFFFFFFu, v, off);
    if ((t & 31) == 0) wsum[t >> 5] = v;
    __syncthreads();

    if (t < 32) {
        float w = (t < NT / 32) ? wsum[t] : 0.0f;
        #pragma unroll
        for (int off = 4; off > 0; off >>= 1)
            w += __shfl_down_sync(0xFFFFFFFFu, w, off);
        if (t == 0) out[0] = w;
    }
}

extern "C" void kernel_launch(void* const* d_in, const int* in_sizes, int n_in,
                              void* d_out, int out_size) {
    const int*   x = (const int*)d_in[0];
    const float* E = (const float*)d_in[1];
    const float* R = (const float*)d_in[2];
    float* out = (float*)d_out;
    holo_kernel<<<1, NT>>>(x, E, R, out);
}